// round 15
// baseline (speedup 1.0000x reference)
#include <cuda_runtime.h>
#include <math_constants.h>

typedef unsigned int u32;

// img (1,200,200,512) f32 NHWC, rois (1,128,4) f32 (x,y,w,h), pool 7x7
// out (1,128,7,7,512) f32.
#define IMG_H 200
#define IMG_W 200
#define IMG_C 512
#define C4    128               // float4 per full pixel record
#define POOLP 7
#define NROIS 128
#define NBINS 49
#define NBIN_TOT (NROIS * NBINS)   // 6272

#define TW 20
#define TH 20
#define NTX 10
#define NTY 10
#define NTILES (NTX * NTY)      // 100

#define NCHUNK 8                // channel chunks per tile (64 ch each)
#define CH4    16               // float4 per chunk per pixel
#define SLAB   (TH * TW * CH4)  // 6400 float4 = 102.4 KB

#define LCAP   512              // SMEM worklist entries (avg ~97/tile)
#define OCAP   (NBIN_TOT - LCAP)

// ---- device scratch (static: allocation-free) ----------------------------
// Private per-CTA overflow spill (no cross-CTA ordering races).
__device__ uint2  g_ovf[NTILES * NCHUNK][OCAP];               // 36.9 MB
// Partial maxima for bins spanning >1 tile: [bin][sy*2+sx][128 float4].
// Only written subslots are ever read -> no init needed.
__device__ float4 g_partial[(size_t)NBIN_TOT * 4 * C4];       // 51.4 MB

// Exact JAX f32 boundary: step = w/7; b[k] = int(x + k*step); mul->add, no fma.
__device__ __forceinline__ int bin_edge(float base, float step, int k) {
    return (int)__fadd_rn(base, __fmul_rn((float)k, step));
}

// ---- kernel 1: fused list-build + stage + sweep --------------------------
// CTA = (20x20 tile, 64-channel chunk), 256 threads, 2 CTAs/SM.
// Warp lane = px(2) x c(16): each LDS.128 is a contiguous 512 B
// conflict-free wavefront set; one xor-16 shuffle folds the pixel pair.
__global__ __launch_bounds__(256, 2) void tile_kernel(const float4* __restrict__ img4,
                                                      const float* __restrict__ rois,
                                                      float4* __restrict__ out4)
{
    extern __shared__ float4 smem[];
    float4* tilebuf = smem;                       // SLAB float4
    uint2*  s_list  = (uint2*)(smem + SLAB);      // LCAP entries

    __shared__ short s_bx[NROIS][8];
    __shared__ short s_by[NROIS][8];
    __shared__ unsigned char s_hit[NROIS];
    __shared__ int s_nhit, s_cnt, s_next;

    const int tid   = threadIdx.x;
    const int chunk = blockIdx.x & (NCHUNK - 1);
    const int tile  = blockIdx.x >> 3;
    const int tx = tile % NTX, ty = tile / NTX;
    const int x0 = tx * TW,    y0 = ty * TH;

    if (tid == 0) { s_nhit = 0; s_cnt = 0; s_next = 0; }
    __syncthreads();

    // -- phase A (threads 0..127): ROI bounds + bbox test ------------------
    if (tid < NROIS) {
        const int r = tid;
        float rx = rois[r * 4 + 0], ry = rois[r * 4 + 1];
        float rw = rois[r * 4 + 2], rh = rois[r * 4 + 3];
        float sx = __fdiv_rn(rw, 7.0f);
        float sy = __fdiv_rn(rh, 7.0f);
        int b0x = 0, b7x = 0, b0y = 0, b7y = 0;
        #pragma unroll
        for (int k = 0; k < 8; k++) {
            int vx = bin_edge(rx, sx, k);
            int vy = bin_edge(ry, sy, k);
            s_bx[r][k] = (short)vx;
            s_by[r][k] = (short)vy;
            if (k == 0) { b0x = vx; b0y = vy; }
            if (k == 7) { b7x = vx; b7y = vy; }
        }
        if (b0x < x0 + TW && b7x > x0 && b0y < y0 + TH && b7y > y0) {
            int idx = atomicAdd(&s_nhit, 1);
            s_hit[idx] = (unsigned char)r;
        }
    }

    // -- stage slab (all threads; overlaps phase-A latency) ----------------
    {
        const float4* __restrict__ src = img4 + chunk * CH4;
        #pragma unroll 5
        for (int i = tid; i < SLAB; i += 256) {
            int p = i >> 4;                       // pixel 0..399
            int c = i & 15;
            int py = p / TW;
            int px = p - py * TW;
            tilebuf[i] = src[((y0 + py) * IMG_W + (x0 + px)) * C4 + c];
        }
    }
    __syncthreads();

    // -- phase B: expand hit ROIs' bins into worklist ----------------------
    const int units = s_nhit * NBINS;
    for (int u = tid; u < units; u += 256) {
        int r   = s_hit[u / NBINS];
        int bin = u % NBINS;
        int jy  = bin / POOLP;
        int ix  = bin - jy * POOLP;
        int rx0 = s_bx[r][ix], rx1 = s_bx[r][ix + 1];
        int ry0 = s_by[r][jy], ry1 = s_by[r][jy + 1];

        int cl = max(rx0 - x0, 0), ch = min(rx1 - x0, TW);
        int rl = max(ry0 - y0, 0), rh = min(ry1 - y0, TH);
        if (cl < ch && rl < rh) {
            int tx0 = rx0 / TW, ty0 = ry0 / TH;
            bool single = (tx0 == (rx1 - 1) / TW) && (ty0 == (ry1 - 1) / TH);
            int bid = r * NBINS + bin;
            u32 dst = single ? ((u32)bid | 0x80000000u)
                             : (u32)(bid * 4 + (ty - ty0) * 2 + (tx - tx0));
            uint2 en = make_uint2(
                (u32)rl | ((u32)rh << 5) | ((u32)cl << 10) | ((u32)ch << 15),
                dst);
            int idx = atomicAdd(&s_cnt, 1);
            if (idx < LCAP) s_list[idx] = en;
            else            g_ovf[blockIdx.x][idx - LCAP] = en;
        }
    }
    __syncthreads();
    const int n = s_cnt;

    // -- sweep: dynamic warp ticket over entries ---------------------------
    const int lane = tid & 31;
    const int c    = lane & 15;                   // channel float4 slot
    const int px   = lane >> 4;                   // pixel offset 0/1

    for (;;) {
        int e;
        if (lane == 0) e = atomicAdd(&s_next, 1);
        e = __shfl_sync(0xffffffffu, e, 0);
        if (e >= n) break;

        uint2 en = (e < LCAP) ? s_list[e] : g_ovf[blockIdx.x][e - LCAP];
        int rl = en.x & 31, rh = (en.x >> 5) & 31;
        int cl = (en.x >> 10) & 31, ch = (en.x >> 15) & 31;
        int nx = ch - cl;

        float4 m = make_float4(-CUDART_INF_F, -CUDART_INF_F,
                               -CUDART_INF_F, -CUDART_INF_F);
        for (int y = rl; y < rh; y++) {
            const float4* rp = tilebuf + (y * TW + cl) * CH4 + c;
            for (int xb = 0; xb < nx; xb += 2) {
                int xx = xb + px;
                if (xx < nx) {
                    float4 v = rp[xx * CH4];
                    m.x = fmaxf(m.x, v.x); m.y = fmaxf(m.y, v.y);
                    m.z = fmaxf(m.z, v.z); m.w = fmaxf(m.w, v.w);
                }
            }
        }
        // fold the pixel pair (xor 16)
        m.x = fmaxf(m.x, __shfl_xor_sync(0xffffffffu, m.x, 16));
        m.y = fmaxf(m.y, __shfl_xor_sync(0xffffffffu, m.y, 16));
        m.z = fmaxf(m.z, __shfl_xor_sync(0xffffffffu, m.z, 16));
        m.w = fmaxf(m.w, __shfl_xor_sync(0xffffffffu, m.w, 16));

        if (px == 0) {
            float4* dst = (en.y & 0x80000000u)
                        ? out4 + (size_t)(en.y & 0x7fffffffu) * C4
                        : g_partial + (size_t)en.y * C4;
            dst[chunk * CH4 + c] = m;             // 256 B coalesced (16 lanes)
        }
    }
}

// ---- kernel 2: combine split-bin partials (4 bins per CTA) ---------------
__global__ __launch_bounds__(128) void reduce_kernel(const float* __restrict__ rois,
                                                     float4* __restrict__ out4)
{
    const int tid = threadIdx.x;
    #pragma unroll 1
    for (int k = 0; k < 4; k++) {
        int bid = blockIdx.x * 4 + k;
        if (bid >= NBIN_TOT) break;
        int r   = bid / NBINS;
        int bin = bid - r * NBINS;
        int jy  = bin / POOLP;
        int ix  = bin - jy * POOLP;

        float rx = rois[r * 4 + 0], ry = rois[r * 4 + 1];
        float rw = rois[r * 4 + 2], rh = rois[r * 4 + 3];
        float sx = __fdiv_rn(rw, 7.0f);
        float sy = __fdiv_rn(rh, 7.0f);
        int bx0 = bin_edge(rx, sx, ix), bx1 = bin_edge(rx, sx, ix + 1);
        int by0 = bin_edge(ry, sy, jy), by1 = bin_edge(ry, sy, jy + 1);

        int ntx = (bx1 - 1) / TW - bx0 / TW + 1;  // 1 or 2
        int nty = (by1 - 1) / TH - by0 / TH + 1;  // 1 or 2
        if (ntx == 1 && nty == 1) continue;       // tile kernel wrote directly

        float4 m = make_float4(-CUDART_INF_F, -CUDART_INF_F,
                               -CUDART_INF_F, -CUDART_INF_F);
        #pragma unroll 1
        for (int sy2 = 0; sy2 < nty; sy2++)
            #pragma unroll 1
            for (int sx2 = 0; sx2 < ntx; sx2++) {
                float4 v = g_partial[(size_t)(bid * 4 + sy2 * 2 + sx2) * C4 + tid];
                m.x = fmaxf(m.x, v.x); m.y = fmaxf(m.y, v.y);
                m.z = fmaxf(m.z, v.z); m.w = fmaxf(m.w, v.w);
            }
        out4[(size_t)bid * C4 + tid] = m;
    }
}

// ---- launch --------------------------------------------------------------
extern "C" void kernel_launch(void* const* d_in, const int* in_sizes, int n_in,
                              void* d_out, int out_size)
{
    const float* img  = (const float*)d_in[0];
    const float* rois = (const float*)d_in[1];
    float4* out = (float4*)d_out;

    const int smem_bytes = SLAB * (int)sizeof(float4)        // 102400
                         + LCAP * (int)sizeof(uint2);        // 4096
    cudaFuncSetAttribute(tile_kernel,
                         cudaFuncAttributeMaxDynamicSharedMemorySize, smem_bytes);

    tile_kernel<<<NTILES * NCHUNK, 256, smem_bytes>>>((const float4*)img, rois, out);
    reduce_kernel<<<(NBIN_TOT + 3) / 4, 128>>>(rois, out);
}

// round 16
// speedup vs baseline: 1.4143x; 1.4143x over previous
#include <cuda_runtime.h>
#include <math_constants.h>

typedef unsigned int u32;

// img (1,200,200,512) f32 NHWC, rois (1,128,4) f32 (x,y,w,h), pool 7x7
// out (1,128,7,7,512) f32.
#define IMG_H 200
#define IMG_W 200
#define IMG_C 512
#define C4    128               // float4 per full pixel record
#define POOLP 7
#define NROIS 128
#define NBINS 49
#define NBIN_TOT (NROIS * NBINS)   // 6272

#define TW 20
#define TH 10
#define NTX (IMG_W / TW)        // 10
#define NTY (IMG_H / TH)        // 20
#define NTILES (NTX * NTY)      // 200

#define NCHUNK 4                // channel chunks per tile (128 ch each)
#define CH4    32               // float4 per chunk per pixel
#define SLAB   (TH * TW * CH4)  // 6400 float4 = 102.4 KB

#define LCAP   256              // SMEM worklist entries (avg ~56/tile)

// ---- device scratch (static: allocation-free) ----------------------------
__device__ int    g_listcnt[NTILES];
__device__ uint2  g_list[NTILES][NBIN_TOT];   // provable cap; 10 MB
__device__ unsigned char g_splitinfo[NBIN_TOT]; // ntx | nty<<4 (home tile writes)
// Partial maxima for bins spanning >1 tile: [bin][sy*2+sx][128 float4].
// Only written subslots are ever read -> no init needed.
__device__ float4 g_partial[(size_t)NBIN_TOT * 4 * C4];   // 51.4 MB

// Exact JAX f32 boundary: step = w/7; b[k] = int(x + k*step); mul->add, no fma.
__device__ __forceinline__ int bin_edge(float base, float step, int k) {
    return (int)__fadd_rn(base, __fmul_rn((float)k, step));
}

// ---- kernel 1: per-tile worklists (CTA per tile, bbox-pruned) ------------
__global__ __launch_bounds__(128) void list_kernel(const float* __restrict__ rois)
{
    __shared__ short s_bx[NROIS][8];
    __shared__ short s_by[NROIS][8];
    __shared__ unsigned char s_hit[NROIS];
    __shared__ int s_nhit, s_cnt;

    const int tid  = threadIdx.x;
    const int tile = blockIdx.x;
    const int tx = tile % NTX, ty = tile / NTX;
    const int x0 = tx * TW,    y0 = ty * TH;

    if (tid == 0) { s_nhit = 0; s_cnt = 0; }
    __syncthreads();

    // phase A: bounds for all ROIs + bbox test vs this tile
    {
        const int r = tid;
        float rx = __ldg(&rois[r * 4 + 0]), ry = __ldg(&rois[r * 4 + 1]);
        float rw = __ldg(&rois[r * 4 + 2]), rh = __ldg(&rois[r * 4 + 3]);
        float sx = __fdiv_rn(rw, 7.0f);
        float sy = __fdiv_rn(rh, 7.0f);
        int b0x = 0, b7x = 0, b0y = 0, b7y = 0;
        #pragma unroll
        for (int k = 0; k < 8; k++) {
            int vx = bin_edge(rx, sx, k);
            int vy = bin_edge(ry, sy, k);
            s_bx[r][k] = (short)vx;
            s_by[r][k] = (short)vy;
            if (k == 0) { b0x = vx; b0y = vy; }
            if (k == 7) { b7x = vx; b7y = vy; }
        }
        if (b0x < x0 + TW && b7x > x0 && b0y < y0 + TH && b7y > y0) {
            int idx = atomicAdd(&s_nhit, 1);
            s_hit[idx] = (unsigned char)r;
        }
    }
    __syncthreads();

    // phase B: expand hit ROIs' bins
    const int units = s_nhit * NBINS;
    for (int u = tid; u < units; u += 128) {
        int r   = s_hit[u / NBINS];
        int bin = u % NBINS;
        int jy  = bin / POOLP;
        int ix  = bin - jy * POOLP;
        int rx0 = s_bx[r][ix], rx1 = s_bx[r][ix + 1];
        int ry0 = s_by[r][jy], ry1 = s_by[r][jy + 1];

        int cl = max(rx0 - x0, 0), ch = min(rx1 - x0, TW);
        int rl = max(ry0 - y0, 0), rh = min(ry1 - y0, TH);
        if (cl < ch && rl < rh) {
            int tx0 = rx0 / TW, ty0 = ry0 / TH;
            int ntx = (rx1 - 1) / TW - tx0 + 1;    // 1 or 2
            int nty = (ry1 - 1) / TH - ty0 + 1;    // 1 or 2
            int bid = r * NBINS + bin;
            // home tile (containing bin's top-left) publishes split info once
            if (tx == tx0 && ty == ty0)
                g_splitinfo[bid] = (unsigned char)(ntx | (nty << 4));
            bool single = (ntx == 1) && (nty == 1);
            u32 dst = single ? ((u32)bid | 0x80000000u)
                             : (u32)(bid * 4 + (ty - ty0) * 2 + (tx - tx0));
            int idx = atomicAdd(&s_cnt, 1);
            g_list[tile][idx] = make_uint2(
                (u32)rl | ((u32)rh << 5) | ((u32)cl << 10) | ((u32)ch << 15),
                dst);
        }
    }
    __syncthreads();
    if (tid == 0) g_listcnt[tile] = s_cnt;
}

// ---- kernel 2: tile sweep ------------------------------------------------
// CTA = (20x10 tile, 128-channel chunk), 512 threads, 102.4 KB slab,
// 2 CTAs/SM (stage of one overlaps sweep of the other). Warp per entry,
// lane = channel: every pixel is one 512 B conflict-free LDS.128 per warp.
// No predication, no shuffles.
__global__ __launch_bounds__(512, 2) void tile_kernel(const float4* __restrict__ img4,
                                                      float4* __restrict__ out4)
{
    extern __shared__ float4 smem[];
    float4* tilebuf = smem;                       // SLAB float4
    uint2*  s_list  = (uint2*)(smem + SLAB);      // LCAP entries
    __shared__ int s_next;

    const int tid   = threadIdx.x;
    const int chunk = blockIdx.x & (NCHUNK - 1);
    const int tile  = blockIdx.x >> 2;
    const int tx = tile % NTX, ty = tile / NTX;
    const int x0 = tx * TW,    y0 = ty * TH;

    if (tid == 0) s_next = 0;

    // -- stage slab: 6400 float4, coalesced 512 B/warp ---------------------
    {
        const float4* __restrict__ src = img4 + chunk * CH4;
        #pragma unroll 4
        for (int i = tid; i < SLAB; i += 512) {
            int p = i >> 5;                       // pixel 0..199
            int c = i & 31;
            int py = p / TW;
            int px = p - py * TW;
            tilebuf[i] = src[((y0 + py) * IMG_W + (x0 + px)) * C4 + c];
        }
    }
    const int n = g_listcnt[tile];
    const uint2* __restrict__ glst = g_list[tile];
    for (int e = tid; e < n && e < LCAP; e += 512)
        s_list[e] = glst[e];
    __syncthreads();

    const int lane = tid & 31;                    // channel float4 slot

    for (;;) {
        int e;
        if (lane == 0) e = atomicAdd(&s_next, 1);
        e = __shfl_sync(0xffffffffu, e, 0);
        if (e >= n) break;

        uint2 en = (e < LCAP) ? s_list[e] : __ldg(&glst[e]);
        int rl = en.x & 31, rh = (en.x >> 5) & 31;
        int cl = (en.x >> 10) & 31, ch = (en.x >> 15) & 31;
        int nx = ch - cl;

        float4 m0 = make_float4(-CUDART_INF_F, -CUDART_INF_F,
                                -CUDART_INF_F, -CUDART_INF_F);
        float4 m1 = m0;
        for (int y = rl; y < rh; y++) {
            const float4* rp = tilebuf + (y * TW + cl) * CH4 + lane;
            int x = 0;
            for (; x + 1 < nx; x += 2) {          // 2 accumulators (ILP)
                float4 v0 = rp[x * CH4];
                float4 v1 = rp[(x + 1) * CH4];
                m0.x = fmaxf(m0.x, v0.x); m0.y = fmaxf(m0.y, v0.y);
                m0.z = fmaxf(m0.z, v0.z); m0.w = fmaxf(m0.w, v0.w);
                m1.x = fmaxf(m1.x, v1.x); m1.y = fmaxf(m1.y, v1.y);
                m1.z = fmaxf(m1.z, v1.z); m1.w = fmaxf(m1.w, v1.w);
            }
            if (x < nx) {
                float4 v0 = rp[x * CH4];
                m0.x = fmaxf(m0.x, v0.x); m0.y = fmaxf(m0.y, v0.y);
                m0.z = fmaxf(m0.z, v0.z); m0.w = fmaxf(m0.w, v0.w);
            }
        }
        m0.x = fmaxf(m0.x, m1.x); m0.y = fmaxf(m0.y, m1.y);
        m0.z = fmaxf(m0.z, m1.z); m0.w = fmaxf(m0.w, m1.w);

        float4* dst = (en.y & 0x80000000u)
                    ? out4 + (size_t)(en.y & 0x7fffffffu) * C4
                    : g_partial + (size_t)en.y * C4;
        dst[chunk * CH4 + lane] = m0;             // 512 B coalesced store
    }
}

// ---- kernel 3: combine split-bin partials (1-byte info, no FP math) ------
__global__ __launch_bounds__(128) void reduce_kernel(float4* __restrict__ out4)
{
    const int bid = blockIdx.x;
    unsigned char info = g_splitinfo[bid];
    int ntx = info & 15, nty = info >> 4;
    if (ntx == 1 && nty == 1) return;             // tile kernel wrote directly

    const int tid = threadIdx.x;
    float4 m = make_float4(-CUDART_INF_F, -CUDART_INF_F,
                           -CUDART_INF_F, -CUDART_INF_F);
    #pragma unroll 1
    for (int sy = 0; sy < nty; sy++)
        #pragma unroll 1
        for (int sx = 0; sx < ntx; sx++) {
            float4 v = g_partial[(size_t)(bid * 4 + sy * 2 + sx) * C4 + tid];
            m.x = fmaxf(m.x, v.x); m.y = fmaxf(m.y, v.y);
            m.z = fmaxf(m.z, v.z); m.w = fmaxf(m.w, v.w);
        }
    out4[(size_t)bid * C4 + tid] = m;
}

// ---- launch --------------------------------------------------------------
extern "C" void kernel_launch(void* const* d_in, const int* in_sizes, int n_in,
                              void* d_out, int out_size)
{
    const float* img  = (const float*)d_in[0];
    const float* rois = (const float*)d_in[1];
    float4* out = (float4*)d_out;

    const int smem_bytes = SLAB * (int)sizeof(float4)        // 102400
                         + LCAP * (int)sizeof(uint2);        // 2048
    cudaFuncSetAttribute(tile_kernel,
                         cudaFuncAttributeMaxDynamicSharedMemorySize, smem_bytes);

    list_kernel<<<NTILES, 128>>>(rois);
    tile_kernel<<<NTILES * NCHUNK, 512, smem_bytes>>>((const float4*)img, out);
    reduce_kernel<<<NBIN_TOT, 128>>>(out);
}